// round 6
// baseline (speedup 1.0000x reference)
#include <cuda_runtime.h>
#include <cuda_fp16.h>

// Problem constants (fixed by the reference)
#define Nn   10000      // nodes
#define Ee   80000      // edges (excl. self loops)
#define Gg   16         // B*DAYS graphs
#define HC   128        // H*C_OUT
#define NEG  0.2f
#define GC   4          // graphs per warp in k_gat
#define PR   8          // rows per block in k_proj
#define NPROJ (Nn / PR)             // 1250 proj blocks
#define NHIST ((Ee + 127) / 128)    // 625 hist blocks
#define LOG2E 1.44269504088896f

// ---- device scratch (allocation-free rule: __device__ globals) ----
__device__ __align__(16) __half g_emb_h[Nn * HC];     // fp16 projected embedding [N,128]
__device__ __align__(16) float g_asrc[Nn * 4];        // per-row src logits * log2e [N,H]
__device__ __align__(16) float g_adst[Nn * 4];        // per-row dst logits * log2e [N,H]
__device__ __align__(16) int g_xT[Nn * Gg];           // transposed x: [N,16]
__device__ int g_row_ptr[Nn + 1];
__device__ int g_cursor[Nn];                          // INVARIANT: all-zero at kernel_launch entry
                                                      // (zero at load; k_gat re-zeroes each launch)
__device__ int g_edge_src[Ee + 1];                    // +1 pad (stays 0) for branch-free prefetch

// ---------------- fused projection + histogram ----------------
// blocks [0, NPROJ): project 8 embedding rows; compute scaled logits; build xT
// blocks [NPROJ, NPROJ+NHIST): histogram edge dst counts into g_cursor
__global__ void __launch_bounds__(128) k_projhist(const float* __restrict__ emb,
                                                  const float* __restrict__ W,
                                                  const float* __restrict__ att_s,
                                                  const float* __restrict__ att_d,
                                                  const int* __restrict__ x,
                                                  const int* __restrict__ adj) {
    int c = threadIdx.x;  // 0..127

    if (blockIdx.x >= NPROJ) {
        int e = (blockIdx.x - NPROJ) * 128 + c;
        if (e < Ee) atomicAdd(&g_cursor[adj[Ee + e]], 1);  // adj[1] = dst
        return;
    }

    int n0 = blockIdx.x * PR;

    // W column for this channel, once per block
    float wcol[32];
#pragma unroll
    for (int k = 0; k < 32; k++) wcol[k] = W[k * 128 + c];

    // 8 embedding rows, coalesced (256 floats / 128 threads)
    __shared__ float se[PR][32];
    __shared__ float sws[32 * 8];   // fused W@att: [k][(srcdst<<2)|h]
#pragma unroll
    for (int i = 0; i < 2; i++) {
        int idx = i * 128 + c;
        se[idx >> 5][idx & 31] = emb[n0 * 32 + idx];
    }

    // redundant per-block ws: ws[k][j] = sum_c W[k,h*32+c]*att[h,c]
#pragma unroll
    for (int t = c; t < 256; t += 128) {
        int k = t >> 3, j = t & 7, h = j & 3;
        const float* av = (j < 4) ? att_s : att_d;
        float a = 0.f;
#pragma unroll
        for (int c2 = 0; c2 < 32; c2++)
            a = fmaf(W[k * 128 + h * 32 + c2], av[h * 32 + c2], a);
        sws[t] = a;
    }

    // x transpose (8 consecutive n per graph g)
    {
        int g = c >> 3, i = c & 7;
        g_xT[(n0 + i) * Gg + g] = x[g * Nn + n0 + i];
    }
    __syncthreads();

    // projected embedding, fp16
#pragma unroll
    for (int r = 0; r < PR; r++) {
        float acc = 0.f;
#pragma unroll
        for (int k = 0; k < 32; k++) acc = fmaf(se[r][k], wcol[k], acc);
        g_emb_h[(n0 + r) * 128 + c] = __float2half(acc);
    }

    // scaled logits: 64 dots (8 rows x 8 cols), pre-multiplied by log2(e)
    if (c < 64) {
        int r = c >> 3, j = c & 7, h = j & 3;
        float acc = 0.f;
#pragma unroll
        for (int k = 0; k < 32; k++) acc = fmaf(se[r][k], sws[k * 8 + j], acc);
        acc *= LOG2E;
        if (j < 4) g_asrc[(n0 + r) * 4 + h] = acc;
        else       g_adst[(n0 + r) * 4 + h] = acc;
    }
}

// ---------------- single-block exclusive scan: g_cursor -> g_row_ptr (+copy) ----------------
__global__ void k_scan() {
    const int CH = 10;  // 1024*10 >= 10000
    __shared__ int part[1024];
    int t = threadIdx.x;
    int base = t * CH;
    int loc[CH];
    int sum = 0;
#pragma unroll
    for (int i = 0; i < CH; i++) {
        int idx = base + i;
        int v = (idx < Nn) ? g_cursor[idx] : 0;
        loc[i] = sum;
        sum += v;
    }
    part[t] = sum;
    __syncthreads();
    for (int off = 1; off < 1024; off <<= 1) {
        int v = (t >= off) ? part[t - off] : 0;
        __syncthreads();
        part[t] += v;
        __syncthreads();
    }
    int prev = (t > 0) ? part[t - 1] : 0;
#pragma unroll
    for (int i = 0; i < CH; i++) {
        int idx = base + i;
        if (idx < Nn) {
            int p = prev + loc[i];
            g_row_ptr[idx] = p;
            g_cursor[idx] = p;
        }
    }
    if (t == 0) g_row_ptr[Nn] = part[1023];
}

// ---------------- CSR fill ----------------
__global__ void k_fill(const int* __restrict__ adj) {
    int e = blockIdx.x * blockDim.x + threadIdx.x;
    if (e < Ee) {
        int d = adj[Ee + e];
        int p = atomicAdd(&g_cursor[d], 1);
        g_edge_src[p] = adj[e];  // adj[0] = src
    }
}

// ---------------- main GAT kernel: one warp per (4-graph chunk, dst node) ----------------
__device__ __forceinline__ float4 load_msg(int u, int lane) {
    uint2 q = *(const uint2*)(g_emb_h + u * 128 + 4 * lane);  // one LDG.64, 8B aligned
    float2 a = __half22float2(*(__half2*)&q.x);
    float2 b = __half22float2(*(__half2*)&q.y);
    return make_float4(a.x, a.y, b.x, b.y);
}

__global__ void __launch_bounds__(256) k_gat(const float* __restrict__ bias,
                                             float* __restrict__ out) {
    int gid = blockIdx.x * blockDim.x + threadIdx.x;
    if (gid < Nn) g_cursor[gid] = 0;   // restore invariant for next launch/replay

    int w = gid >> 5;
    int lane = threadIdx.x & 31;
    const int NW = Nn * (Gg / GC);
    if (w >= NW) return;
    int v = w >> 2;          // adjacent warps share v -> L1 hits on structure
    int gc = w & 3;          // graph chunk: graphs gc*4 .. gc*4+3
    int h = lane >> 3;

    int4 vx = *(const int4*)(g_xT + v * Gg + gc * GC);
    int vemb[GC] = {vx.x, vx.y, vx.z, vx.w};

    float adst[GC], s[GC];
    float4 acc[GC];
#pragma unroll
    for (int i = 0; i < GC; i++) {
        adst[i] = g_adst[vemb[i] * 4 + h];
        float a0 = g_asrc[vemb[i] * 4 + h] + adst[i];
        a0 = fmaxf(a0, NEG * a0);
        float e0 = exp2f(a0);
        s[i] = e0;
        float4 m = load_msg(vemb[i], lane);
        acc[i] = make_float4(e0 * m.x, e0 * m.y, e0 * m.z, e0 * m.w);
    }

    int idx = g_row_ptr[v];
    int end = g_row_ptr[v + 1];
    // branch-free software pipeline: always prefetch idx+1 (pad slot reads 0 -> node 0, discarded)
    int j0 = g_edge_src[idx];
    int4 ux = *(const int4*)(g_xT + j0 * Gg + gc * GC);
    while (idx < end) {
        int jn = g_edge_src[idx + 1];
        int4 uxn = *(const int4*)(g_xT + jn * Gg + gc * GC);
        int u[GC] = {ux.x, ux.y, ux.z, ux.w};
        float a[GC];
        float4 m[GC];
#pragma unroll
        for (int i = 0; i < GC; i++) {
            a[i] = g_asrc[u[i] * 4 + h] + adst[i];
            m[i] = load_msg(u[i], lane);
        }
#pragma unroll
        for (int i = 0; i < GC; i++) {
            float ai = fmaxf(a[i], NEG * a[i]);
            float wi = exp2f(ai);
            s[i] += wi;
            acc[i].x = fmaf(wi, m[i].x, acc[i].x);
            acc[i].y = fmaf(wi, m[i].y, acc[i].y);
            acc[i].z = fmaf(wi, m[i].z, acc[i].z);
            acc[i].w = fmaf(wi, m[i].w, acc[i].w);
        }
        ux = uxn;
        idx++;
    }

    float4 b = *(const float4*)(bias + 4 * lane);
#pragma unroll
    for (int i = 0; i < GC; i++) {
        float inv = __fdividef(1.f, s[i] + 1e-16f);
        float4 o;
        o.x = fmaf(acc[i].x, inv, b.x);
        o.y = fmaf(acc[i].y, inv, b.y);
        o.z = fmaf(acc[i].z, inv, b.z);
        o.w = fmaf(acc[i].w, inv, b.w);
        int g = gc * GC + i;
        *(float4*)(out + ((size_t)g * Nn + v) * 128 + 4 * lane) = o;
    }
}

extern "C" void kernel_launch(void* const* d_in, const int* in_sizes, int n_in,
                              void* d_out, int out_size) {
    const int*   x     = (const int*)d_in[0];     // [B,DAYS,N] = [16,10000]
    const int*   adj   = (const int*)d_in[1];     // [2,E]
    const float* emb   = (const float*)d_in[2];   // [N,32]
    const float* W     = (const float*)d_in[3];   // [32,128]
    const float* att_s = (const float*)d_in[4];   // [4,32]
    const float* att_d = (const float*)d_in[5];   // [4,32]
    const float* bias  = (const float*)d_in[6];   // [128]
    float* out = (float*)d_out;                   // [16,10000,128]

    k_projhist<<<NPROJ + NHIST, 128>>>(emb, W, att_s, att_d, x, adj);
    k_scan<<<1, 1024>>>();
    k_fill<<<(Ee + 255) / 256, 256>>>(adj);

    int total_warps = Nn * (Gg / GC);
    k_gat<<<(total_warps * 32 + 255) / 256, 256>>>(bias, out);
}

// round 7
// speedup vs baseline: 1.0663x; 1.0663x over previous
#include <cuda_runtime.h>
#include <cuda_fp16.h>

// Problem constants (fixed by the reference)
#define Nn   10000      // nodes
#define Ee   80000      // edges (excl. self loops)
#define Gg   16         // B*DAYS graphs
#define HC   128        // H*C_OUT
#define NEG  0.2f
#define PR   8          // rows per block in k_proj
#define NPROJ (Nn / PR)             // 1250 proj blocks
#define NHIST ((Ee + 127) / 128)    // 625 hist blocks
#define LOG2E 1.44269504088896f

// ---- device scratch (allocation-free rule: __device__ globals) ----
__device__ __align__(16) __half g_emb_h[Nn * HC];     // fp16 projected embedding [N,128]
__device__ __align__(16) float g_asrc[Nn * 4];        // per-row src logits * log2e [N,H]
__device__ __align__(16) float g_adst[Nn * 4];        // per-row dst logits * log2e [N,H]
__device__ __align__(16) int g_xT[Nn * Gg];           // transposed x: [N,16]
__device__ int g_row_ptr[Nn + 1];
__device__ int g_cursor[Nn];                          // INVARIANT: all-zero at kernel_launch entry
                                                      // (zero at load; k_gat re-zeroes each launch)
__device__ int g_edge_src[Ee + 2];                    // +2 pad (stays 0) for 2-deep prefetch

__device__ __forceinline__ float fexp2(float x) {
    float y;
    asm("ex2.approx.f32 %0, %1;" : "=f"(y) : "f"(x));
    return y;
}

// ---------------- fused projection + histogram ----------------
__global__ void __launch_bounds__(128) k_projhist(const float* __restrict__ emb,
                                                  const float* __restrict__ W,
                                                  const float* __restrict__ att_s,
                                                  const float* __restrict__ att_d,
                                                  const int* __restrict__ x,
                                                  const int* __restrict__ adj) {
    int c = threadIdx.x;  // 0..127

    if (blockIdx.x >= NPROJ) {
        int e = (blockIdx.x - NPROJ) * 128 + c;
        if (e < Ee) atomicAdd(&g_cursor[adj[Ee + e]], 1);  // adj[1] = dst
        return;
    }

    int n0 = blockIdx.x * PR;

    float wcol[32];
#pragma unroll
    for (int k = 0; k < 32; k++) wcol[k] = W[k * 128 + c];

    __shared__ float se[PR][32];
    __shared__ float sws[32 * 8];   // fused W@att: [k][(srcdst<<2)|h]
#pragma unroll
    for (int i = 0; i < 2; i++) {
        int idx = i * 128 + c;
        se[idx >> 5][idx & 31] = emb[n0 * 32 + idx];
    }

#pragma unroll
    for (int t = c; t < 256; t += 128) {
        int k = t >> 3, j = t & 7, h = j & 3;
        const float* av = (j < 4) ? att_s : att_d;
        float a = 0.f;
#pragma unroll
        for (int c2 = 0; c2 < 32; c2++)
            a = fmaf(W[k * 128 + h * 32 + c2], av[h * 32 + c2], a);
        sws[t] = a;
    }

    {
        int g = c >> 3, i = c & 7;
        g_xT[(n0 + i) * Gg + g] = x[g * Nn + n0 + i];
    }
    __syncthreads();

#pragma unroll
    for (int r = 0; r < PR; r++) {
        float acc = 0.f;
#pragma unroll
        for (int k = 0; k < 32; k++) acc = fmaf(se[r][k], wcol[k], acc);
        g_emb_h[(n0 + r) * 128 + c] = __float2half(acc);
    }

    if (c < 64) {
        int r = c >> 3, j = c & 7, h = j & 3;
        float acc = 0.f;
#pragma unroll
        for (int k = 0; k < 32; k++) acc = fmaf(se[r][k], sws[k * 8 + j], acc);
        acc *= LOG2E;
        if (j < 4) g_asrc[(n0 + r) * 4 + h] = acc;
        else       g_adst[(n0 + r) * 4 + h] = acc;
    }
}

// ---------------- single-block exclusive scan: g_cursor -> g_row_ptr (+copy) ----------------
__global__ void k_scan() {
    const int CH = 10;
    __shared__ int part[1024];
    int t = threadIdx.x;
    int base = t * CH;
    int loc[CH];
    int sum = 0;
#pragma unroll
    for (int i = 0; i < CH; i++) {
        int idx = base + i;
        int v = (idx < Nn) ? g_cursor[idx] : 0;
        loc[i] = sum;
        sum += v;
    }
    part[t] = sum;
    __syncthreads();
    for (int off = 1; off < 1024; off <<= 1) {
        int v = (t >= off) ? part[t - off] : 0;
        __syncthreads();
        part[t] += v;
        __syncthreads();
    }
    int prev = (t > 0) ? part[t - 1] : 0;
#pragma unroll
    for (int i = 0; i < CH; i++) {
        int idx = base + i;
        if (idx < Nn) {
            int p = prev + loc[i];
            g_row_ptr[idx] = p;
            g_cursor[idx] = p;
        }
    }
    if (t == 0) g_row_ptr[Nn] = part[1023];
}

// ---------------- CSR fill ----------------
__global__ void k_fill(const int* __restrict__ adj) {
    int e = blockIdx.x * blockDim.x + threadIdx.x;
    if (e < Ee) {
        int d = adj[Ee + e];
        int p = atomicAdd(&g_cursor[d], 1);
        g_edge_src[p] = adj[e];  // adj[0] = src
    }
}

// ---------------- main GAT kernel ----------------
// Warp = (node v, 4-graph chunk gc). Lane l: graph gi = l>>3 (within chunk),
// sub = l&7 owns 16 channels [16*sub, 16*sub+16) of that graph; head h = sub>>1.
// Per edge per lane: 1 asrc load, 1 lrelu, 1 ex2, 2x LDG.128 message, 16 FMA.
__global__ void __launch_bounds__(256) k_gat(const float* __restrict__ bias,
                                             float* __restrict__ out) {
    int gid = blockIdx.x * blockDim.x + threadIdx.x;
    if (gid < Nn) g_cursor[gid] = 0;   // restore invariant for next launch/replay

    int w = gid >> 5;
    int lane = threadIdx.x & 31;
    const int NW = Nn * 4;
    if (w >= NW) return;
    int v = w >> 2;              // adjacent warps share v -> L1 hits on structure
    int gc = w & 3;              // graph chunk
    int gi = lane >> 3;          // graph within chunk
    int g = gc * 4 + gi;         // global graph id
    int sub = lane & 7;          // channel group: [16*sub, 16*sub+16)
    int h = sub >> 1;            // head

    const __half* __restrict__ embp = g_emb_h;

    int vemb = g_xT[v * Gg + g];
    float adst = g_adst[vemb * 4 + h];

    float acc[16];
    float s;
    {
        float a0 = g_asrc[vemb * 4 + h] + adst;
        a0 = fmaxf(a0, NEG * a0);
        float e0 = fexp2(a0);
        s = e0;
        const uint4* mp = (const uint4*)(embp + vemb * 128 + sub * 16);
        uint4 q0 = mp[0], q1 = mp[1];
        const __half2* hp0 = (const __half2*)&q0;
        const __half2* hp1 = (const __half2*)&q1;
#pragma unroll
        for (int k = 0; k < 4; k++) {
            float2 f0 = __half22float2(hp0[k]);
            float2 f1 = __half22float2(hp1[k]);
            acc[2 * k] = e0 * f0.x;
            acc[2 * k + 1] = e0 * f0.y;
            acc[8 + 2 * k] = e0 * f1.x;
            acc[8 + 2 * k + 1] = e0 * f1.y;
        }
    }

    int idx = g_row_ptr[v];
    int end = g_row_ptr[v + 1];
    // 2-deep software pipeline (edge_src padded by 2 zeros; xT[0*16+g] is valid)
    int j1 = g_edge_src[idx];
    int u_cur = g_xT[j1 * Gg + g];
    int j2 = g_edge_src[idx + 1];
    for (; idx < end; idx++) {
        int u = u_cur;
        // prefetch next iteration
        u_cur = g_xT[j2 * Gg + g];
        j2 = g_edge_src[idx + 2];

        float a = g_asrc[u * 4 + h] + adst;
        const uint4* mp = (const uint4*)(embp + u * 128 + sub * 16);
        uint4 q0 = mp[0], q1 = mp[1];
        a = fmaxf(a, NEG * a);
        float wi = fexp2(a);
        s += wi;
        const __half2* hp0 = (const __half2*)&q0;
        const __half2* hp1 = (const __half2*)&q1;
#pragma unroll
        for (int k = 0; k < 4; k++) {
            float2 f0 = __half22float2(hp0[k]);
            float2 f1 = __half22float2(hp1[k]);
            acc[2 * k]         = fmaf(wi, f0.x, acc[2 * k]);
            acc[2 * k + 1]     = fmaf(wi, f0.y, acc[2 * k + 1]);
            acc[8 + 2 * k]     = fmaf(wi, f1.x, acc[8 + 2 * k]);
            acc[8 + 2 * k + 1] = fmaf(wi, f1.y, acc[8 + 2 * k + 1]);
        }
    }

    float inv = __fdividef(1.f, s + 1e-16f);
    float* op = out + ((size_t)g * Nn + v) * 128 + sub * 16;
    const float* bp = bias + sub * 16;
#pragma unroll
    for (int k = 0; k < 4; k++) {
        float4 b = *(const float4*)(bp + 4 * k);
        float4 o;
        o.x = fmaf(acc[4 * k], inv, b.x);
        o.y = fmaf(acc[4 * k + 1], inv, b.y);
        o.z = fmaf(acc[4 * k + 2], inv, b.z);
        o.w = fmaf(acc[4 * k + 3], inv, b.w);
        *(float4*)(op + 4 * k) = o;
    }
}

extern "C" void kernel_launch(void* const* d_in, const int* in_sizes, int n_in,
                              void* d_out, int out_size) {
    const int*   x     = (const int*)d_in[0];     // [B,DAYS,N] = [16,10000]
    const int*   adj   = (const int*)d_in[1];     // [2,E]
    const float* emb   = (const float*)d_in[2];   // [N,32]
    const float* W     = (const float*)d_in[3];   // [32,128]
    const float* att_s = (const float*)d_in[4];   // [4,32]
    const float* att_d = (const float*)d_in[5];   // [4,32]
    const float* bias  = (const float*)d_in[6];   // [128]
    float* out = (float*)d_out;                   // [16,10000,128]

    k_projhist<<<NPROJ + NHIST, 128>>>(emb, W, att_s, att_d, x, adj);
    k_scan<<<1, 1024>>>();
    k_fill<<<(Ee + 255) / 256, 256>>>(adj);

    int total_warps = Nn * 4;
    k_gat<<<(total_warps * 32 + 255) / 256, 256>>>(bias, out);
}

// round 8
// speedup vs baseline: 1.2472x; 1.1696x over previous
#include <cuda_runtime.h>
#include <cuda_fp16.h>

// Problem constants (fixed by the reference)
#define Nn   10000      // nodes
#define Ee   80000      // edges (excl. self loops)
#define Gg   16         // B*DAYS graphs
#define HC   128        // H*C_OUT
#define NEG  0.2f
#define PR   8          // rows per proj group
#define NPROJ (Nn / PR)             // 1250 proj groups
#define LOG2E 1.44269504088896f

#define GRID  148       // one block per SM -> all blocks co-resident (safe grid barrier)
#define TPB   1024
#define GRPS  8         // 128-thread proj groups per block
#define ITERP ((NPROJ + GRID * GRPS - 1) / (GRID * GRPS))   // 2
#define CHUNK 96        // nodes per block in scan (3 per lane of warp 0)

// ---- device scratch (allocation-free rule: __device__ globals) ----
__device__ __align__(16) __half g_emb_h[Nn * HC];     // fp16 projected embedding [N,128]
__device__ __align__(16) float g_asrc[Nn * 4];        // src logits * log2e [N,H]
__device__ __align__(16) float g_adst[Nn * 4];        // dst logits * log2e [N,H]
__device__ __align__(16) int g_xT[Nn * Gg];           // transposed x: [N,16]
__device__ int g_row_ptr[Nn + 1];
__device__ int g_cursor[Nn];                          // INVARIANT: all-zero at launch entry
__device__ int g_edge_src[Ee + 2];                    // +2 pad (stays 0) for prefetch
__device__ int g_bsum[GRID];

// grid barrier state: count self-resets; gen is monotonic across launches (never
// compared to an absolute value, so replay-safe and deterministic in output)
__device__ unsigned g_bcount = 0;
__device__ volatile unsigned g_bgen = 0;

__device__ __forceinline__ void grid_bar() {
    __syncthreads();
    if (threadIdx.x == 0) {
        __threadfence();
        unsigned my = g_bgen;
        unsigned t = atomicAdd(&g_bcount, 1);
        if (t == GRID - 1) {
            g_bcount = 0;
            __threadfence();
            g_bgen = my + 1;
        } else {
            while (g_bgen == my) { }
            __threadfence();
        }
    }
    __syncthreads();
}

__device__ __forceinline__ float fexp2(float x) {
    float y;
    asm("ex2.approx.f32 %0, %1;" : "=f"(y) : "f"(x));
    return y;
}

__global__ void __launch_bounds__(TPB, 1)
k_all(const float* __restrict__ emb, const float* __restrict__ W,
      const float* __restrict__ att_s, const float* __restrict__ att_d,
      const int* __restrict__ x, const int* __restrict__ adj,
      const float* __restrict__ bias, float* __restrict__ out) {
    int tid = threadIdx.x;
    int b = blockIdx.x;

    __shared__ float sws[256];            // fused W@att: [k][(srcdst<<2)|h]
    __shared__ float se[GRPS][PR][32];
    __shared__ int svals[CHUNK];
    __shared__ int sblk, soff;

    // ================= Phase A: histogram + projection + x-transpose =================
    // histogram (atomics go straight to L2; overlap with proj compute)
    for (int e = b * TPB + tid; e < Ee; e += GRID * TPB)
        atomicAdd(&g_cursor[adj[Ee + e]], 1);          // adj[1] = dst

    // fused attention weights, once per block
    if (tid < 256) {
        int k = tid >> 3, j = tid & 7, h = j & 3;
        const float* av = (j < 4) ? att_s : att_d;
        float a = 0.f;
#pragma unroll
        for (int c2 = 0; c2 < 32; c2++)
            a = fmaf(W[k * 128 + h * 32 + c2], av[h * 32 + c2], a);
        sws[tid] = a;
    }
    __syncthreads();

    {
        int grp = tid >> 7;          // 0..7
        int c = tid & 127;           // channel 0..127
        float wcol[32];
#pragma unroll
        for (int k = 0; k < 32; k++) wcol[k] = W[k * 128 + c];

        for (int it = 0; it < ITERP; it++) {
            int gb = it * (GRID * GRPS) + b * GRPS + grp;
            bool act = gb < NPROJ;
            int n0 = gb * PR;
            if (act) {
#pragma unroll
                for (int i = 0; i < 2; i++) {
                    int idx = i * 128 + c;
                    se[grp][idx >> 5][idx & 31] = emb[n0 * 32 + idx];
                }
                int gg = c >> 3, i = c & 7;
                g_xT[(n0 + i) * Gg + gg] = x[gg * Nn + n0 + i];
            }
            asm volatile("bar.sync %0, %1;" :: "r"(grp + 1), "r"(128));
            if (act) {
#pragma unroll
                for (int r = 0; r < PR; r++) {
                    float acc = 0.f;
#pragma unroll
                    for (int k = 0; k < 32; k++) acc = fmaf(se[grp][r][k], wcol[k], acc);
                    g_emb_h[(n0 + r) * 128 + c] = __float2half(acc);
                }
                if (c < 64) {
                    int r = c >> 3, j = c & 7, h = j & 3;
                    float acc = 0.f;
#pragma unroll
                    for (int k = 0; k < 32; k++) acc = fmaf(se[grp][r][k], sws[k * 8 + j], acc);
                    acc *= LOG2E;
                    if (j < 4) g_asrc[(n0 + r) * 4 + h] = acc;
                    else       g_adst[(n0 + r) * 4 + h] = acc;
                }
            }
            asm volatile("bar.sync %0, %1;" :: "r"(grp + 1), "r"(128));
        }
    }
    grid_bar();   // ---- barrier 1: histogram complete ----

    // ================= Phase B: CSR scan (two-level) =================
    if (tid < 32) {
        int lane = tid;
        int i0 = b * CHUNK + lane * 3;
        int c0 = (i0 < Nn) ? g_cursor[i0] : 0;
        int c1 = (i0 + 1 < Nn) ? g_cursor[i0 + 1] : 0;
        int c2 = (i0 + 2 < Nn) ? g_cursor[i0 + 2] : 0;
        int lsum = c0 + c1 + c2;
        int pre = lsum;
#pragma unroll
        for (int o = 1; o < 32; o <<= 1) {
            int t = __shfl_up_sync(0xffffffffu, pre, o);
            if (lane >= o) pre += t;
        }
        int excl = pre - lsum;
        svals[lane * 3] = excl;
        svals[lane * 3 + 1] = excl + c0;
        svals[lane * 3 + 2] = excl + c0 + c1;
        if (lane == 31) sblk = pre;   // block total
    }
    __syncthreads();
    if (tid == 0) g_bsum[b] = sblk;
    grid_bar();   // ---- barrier 2: all block sums visible ----

    if (tid < 32) {
        int lane = tid;
        int acc = 0;
        for (int i = lane; i < b; i += 32) acc += g_bsum[i];
#pragma unroll
        for (int o = 16; o; o >>= 1) acc += __shfl_down_sync(0xffffffffu, acc, o);
        if (lane == 0) soff = acc;
    }
    __syncthreads();
    {
        int off = soff;
        if (tid < CHUNK) {
            int n = b * CHUNK + tid;
            if (n < Nn) {
                int p = off + svals[tid];
                g_row_ptr[n] = p;
                g_cursor[n] = p;
            }
        }
        if (b == 0 && tid == 0) g_row_ptr[Nn] = Ee;
    }
    grid_bar();   // ---- barrier 3: row_ptr/cursor ready ----

    // ================= Phase C: CSR fill =================
    for (int e = b * TPB + tid; e < Ee; e += GRID * TPB) {
        int d = adj[Ee + e];
        int p = atomicAdd(&g_cursor[d], 1);
        g_edge_src[p] = adj[e];          // adj[0] = src
    }
    grid_bar();   // ---- barrier 4: edge_src ready ----

    // ================= Phase D: GAT (persistent warps) =================
    // restore cursor invariant for next launch/replay
    for (int n = b * TPB + tid; n < Nn; n += GRID * TPB) g_cursor[n] = 0;

    int lane = tid & 31;
    int gi = lane >> 3;          // graph within 4-chunk
    int sub = lane & 7;          // channel group: [16*sub, 16*sub+16)
    int h = sub >> 1;            // head
    const __half* __restrict__ embp = g_emb_h;

    for (int w = b * 32 + (tid >> 5); w < Nn * 4; w += GRID * 32) {
        int v = w >> 2;              // consecutive warps share v -> L1 hits
        int gc = w & 3;
        int g = gc * 4 + gi;

        int vemb = g_xT[v * Gg + g];
        float adst = g_adst[vemb * 4 + h];

        float acc[16];
        float s;
        {
            float a0 = g_asrc[vemb * 4 + h] + adst;
            a0 = fmaxf(a0, NEG * a0);
            float e0 = fexp2(a0);
            s = e0;
            const uint4* mp = (const uint4*)(embp + vemb * 128 + sub * 16);
            uint4 q0 = mp[0], q1 = mp[1];
            const __half2* hp0 = (const __half2*)&q0;
            const __half2* hp1 = (const __half2*)&q1;
#pragma unroll
            for (int k = 0; k < 4; k++) {
                float2 f0 = __half22float2(hp0[k]);
                float2 f1 = __half22float2(hp1[k]);
                acc[2 * k] = e0 * f0.x;
                acc[2 * k + 1] = e0 * f0.y;
                acc[8 + 2 * k] = e0 * f1.x;
                acc[8 + 2 * k + 1] = e0 * f1.y;
            }
        }

        int idx = g_row_ptr[v];
        int end = g_row_ptr[v + 1];
        int j1 = g_edge_src[idx];
        int u_cur = g_xT[j1 * Gg + g];
        int j2 = g_edge_src[idx + 1];
        for (; idx < end; idx++) {
            int u = u_cur;
            u_cur = g_xT[j2 * Gg + g];
            j2 = g_edge_src[idx + 2];

            float a = g_asrc[u * 4 + h] + adst;
            const uint4* mp = (const uint4*)(embp + u * 128 + sub * 16);
            uint4 q0 = mp[0], q1 = mp[1];
            a = fmaxf(a, NEG * a);
            float wi = fexp2(a);
            s += wi;
            const __half2* hp0 = (const __half2*)&q0;
            const __half2* hp1 = (const __half2*)&q1;
#pragma unroll
            for (int k = 0; k < 4; k++) {
                float2 f0 = __half22float2(hp0[k]);
                float2 f1 = __half22float2(hp1[k]);
                acc[2 * k]         = fmaf(wi, f0.x, acc[2 * k]);
                acc[2 * k + 1]     = fmaf(wi, f0.y, acc[2 * k + 1]);
                acc[8 + 2 * k]     = fmaf(wi, f1.x, acc[8 + 2 * k]);
                acc[8 + 2 * k + 1] = fmaf(wi, f1.y, acc[8 + 2 * k + 1]);
            }
        }

        float inv = __fdividef(1.f, s + 1e-16f);
        float* op = out + ((size_t)g * Nn + v) * 128 + sub * 16;
        const float* bp = bias + sub * 16;
#pragma unroll
        for (int k = 0; k < 4; k++) {
            float4 bb = *(const float4*)(bp + 4 * k);
            float4 o;
            o.x = fmaf(acc[4 * k], inv, bb.x);
            o.y = fmaf(acc[4 * k + 1], inv, bb.y);
            o.z = fmaf(acc[4 * k + 2], inv, bb.z);
            o.w = fmaf(acc[4 * k + 3], inv, bb.w);
            *(float4*)(op + 4 * k) = o;
        }
    }
}

extern "C" void kernel_launch(void* const* d_in, const int* in_sizes, int n_in,
                              void* d_out, int out_size) {
    const int*   x     = (const int*)d_in[0];     // [B,DAYS,N] = [16,10000]
    const int*   adj   = (const int*)d_in[1];     // [2,E]
    const float* emb   = (const float*)d_in[2];   // [N,32]
    const float* W     = (const float*)d_in[3];   // [32,128]
    const float* att_s = (const float*)d_in[4];   // [4,32]
    const float* att_d = (const float*)d_in[5];   // [4,32]
    const float* bias  = (const float*)d_in[6];   // [128]
    float* out = (float*)d_out;                   // [16,10000,128]

    k_all<<<GRID, TPB>>>(emb, W, att_s, att_d, x, adj, bias, out);
}

// round 9
// speedup vs baseline: 1.2934x; 1.0371x over previous
#include <cuda_runtime.h>
#include <cuda_fp16.h>

// Problem constants (fixed by the reference)
#define Nn   10000      // nodes
#define Ee   80000      // edges (excl. self loops)
#define Gg   16         // B*DAYS graphs
#define HC   128        // H*C_OUT
#define NEG  0.2f
#define PR   8          // rows per proj group
#define NPROJ (Nn / PR)             // 1250 proj groups
#define LOG2E 1.44269504088896f

#define GRID  148       // one block per SM -> all blocks co-resident (safe grid barrier)
#define TPB   1024
#define GRPS  8         // 128-thread proj groups per block
#define ITERP ((NPROJ + GRID * GRPS - 1) / (GRID * GRPS))   // 2
#define CHUNK 96        // nodes per block in scan (3 per lane of warp 0)

// ---- device scratch (allocation-free rule: __device__ globals) ----
__device__ __align__(16) __half g_emb_h[Nn * HC];     // fp16 projected embedding [N,128]
__device__ __align__(16) float g_asrc[Nn * 4];        // src logits * log2e [N,H]
__device__ __align__(16) float g_adst[Nn * 4];        // dst logits * log2e [N,H]
__device__ __align__(16) int g_xT[Nn * Gg];           // transposed x: [N,16]
__device__ __align__(16) float2 g_comb[Nn * Gg * 4];  // per (n,g,h): {u_bits, asrc[u][h]}
__device__ int g_row_ptr[Nn + 1];
__device__ int g_cursor[Nn];                          // INVARIANT: all-zero at launch entry
__device__ int g_edge_src[Ee + 2];                    // +2 pad (stays 0) for prefetch
__device__ int g_bsum[GRID];

// grid barrier: count self-resets; gen is monotonic across launches (replay-safe)
__device__ unsigned g_bcount = 0;
__device__ volatile unsigned g_bgen = 0;

__device__ __forceinline__ void grid_bar() {
    __syncthreads();
    if (threadIdx.x == 0) {
        __threadfence();
        unsigned my = g_bgen;
        unsigned t = atomicAdd(&g_bcount, 1);
        if (t == GRID - 1) {
            g_bcount = 0;
            __threadfence();
            g_bgen = my + 1;
        } else {
            while (g_bgen == my) { }
            __threadfence();
        }
    }
    __syncthreads();
}

__device__ __forceinline__ float fexp2(float x) {
    float y;
    asm("ex2.approx.f32 %0, %1;" : "=f"(y) : "f"(x));
    return y;
}

__global__ void __launch_bounds__(TPB, 1)
k_all(const float* __restrict__ emb, const float* __restrict__ W,
      const float* __restrict__ att_s, const float* __restrict__ att_d,
      const int* __restrict__ x, const int* __restrict__ adj,
      const float* __restrict__ bias, float* __restrict__ out) {
    int tid = threadIdx.x;
    int b = blockIdx.x;

    __shared__ float sws[256];            // fused W@att: [k][(srcdst<<2)|h]
    __shared__ float se[GRPS][PR][32];
    __shared__ int svals[CHUNK];
    __shared__ int soff;

    // ================= Phase A: histogram + projection + x-transpose =================
    for (int e = b * TPB + tid; e < Ee; e += GRID * TPB)
        atomicAdd(&g_cursor[adj[Ee + e]], 1);          // adj[1] = dst

    if (tid < 256) {
        int k = tid >> 3, j = tid & 7, h = j & 3;
        const float* av = (j < 4) ? att_s : att_d;
        float a = 0.f;
#pragma unroll
        for (int c2 = 0; c2 < 32; c2++)
            a = fmaf(W[k * 128 + h * 32 + c2], av[h * 32 + c2], a);
        sws[tid] = a;
    }
    __syncthreads();

    {
        int grp = tid >> 7;          // 0..7
        int c = tid & 127;           // channel 0..127
        float wcol[32];
#pragma unroll
        for (int k = 0; k < 32; k++) wcol[k] = W[k * 128 + c];

        for (int it = 0; it < ITERP; it++) {
            int gb = it * (GRID * GRPS) + b * GRPS + grp;
            bool act = gb < NPROJ;
            int n0 = gb * PR;
            if (act) {
#pragma unroll
                for (int i = 0; i < 2; i++) {
                    int idx = i * 128 + c;
                    se[grp][idx >> 5][idx & 31] = emb[n0 * 32 + idx];
                }
                int gg = c >> 3, i = c & 7;
                g_xT[(n0 + i) * Gg + gg] = x[gg * Nn + n0 + i];
            }
            asm volatile("bar.sync %0, %1;" :: "r"(grp + 1), "r"(128));
            if (act) {
#pragma unroll
                for (int r = 0; r < PR; r++) {
                    float acc = 0.f;
#pragma unroll
                    for (int k = 0; k < 32; k++) acc = fmaf(se[grp][r][k], wcol[k], acc);
                    g_emb_h[(n0 + r) * 128 + c] = __float2half(acc);
                }
                if (c < 64) {
                    int r = c >> 3, j = c & 7, h = j & 3;
                    float acc = 0.f;
#pragma unroll
                    for (int k = 0; k < 32; k++) acc = fmaf(se[grp][r][k], sws[k * 8 + j], acc);
                    acc *= LOG2E;
                    if (j < 4) g_asrc[(n0 + r) * 4 + h] = acc;
                    else       g_adst[(n0 + r) * 4 + h] = acc;
                }
            }
            asm volatile("bar.sync %0, %1;" :: "r"(grp + 1), "r"(128));
        }
    }
    grid_bar();   // ---- barrier 1: histogram + asrc + xT complete ----

    // ================= Phase B: CSR scan (warp 0) + comb table (all threads) =================
    if (tid < 32) {
        int lane = tid;
        int i0 = b * CHUNK + lane * 3;
        int c0 = (i0 < Nn) ? g_cursor[i0] : 0;
        int c1 = (i0 + 1 < Nn) ? g_cursor[i0 + 1] : 0;
        int c2 = (i0 + 2 < Nn) ? g_cursor[i0 + 2] : 0;
        int lsum = c0 + c1 + c2;
        int pre = lsum;
#pragma unroll
        for (int o = 1; o < 32; o <<= 1) {
            int t = __shfl_up_sync(0xffffffffu, pre, o);
            if (lane >= o) pre += t;
        }
        int excl = pre - lsum;
        svals[lane * 3] = excl;
        svals[lane * 3 + 1] = excl + c0;
        svals[lane * 3 + 2] = excl + c0 + c1;
        if (lane == 31) g_bsum[b] = pre;   // block total
    }

    // comb: per (n,g): u = xT[n*16+g]; entries h=0..3: {u_bits, asrc[u][h]}
    for (int i = b * TPB + tid; i < Nn * Gg; i += GRID * TPB) {
        int u = g_xT[i];
        float4 a4 = *(const float4*)(g_asrc + u * 4);
        float uf = __int_as_float(u);
        float4* dst = (float4*)(g_comb + i * 4);
        dst[0] = make_float4(uf, a4.x, uf, a4.y);
        dst[1] = make_float4(uf, a4.z, uf, a4.w);
    }
    grid_bar();   // ---- barrier 2: block sums + comb visible ----

    if (tid < 32) {
        int lane = tid;
        int acc = 0;
        for (int i = lane; i < b; i += 32) acc += g_bsum[i];
#pragma unroll
        for (int o = 16; o; o >>= 1) acc += __shfl_down_sync(0xffffffffu, acc, o);
        if (lane == 0) soff = acc;
    }
    __syncthreads();
    {
        int off = soff;
        if (tid < CHUNK) {
            int n = b * CHUNK + tid;
            if (n < Nn) {
                int p = off + svals[tid];
                g_row_ptr[n] = p;
                g_cursor[n] = p;
            }
        }
        if (b == 0 && tid == 0) g_row_ptr[Nn] = Ee;
    }
    grid_bar();   // ---- barrier 3: row_ptr/cursor ready ----

    // ================= Phase C: CSR fill =================
    for (int e = b * TPB + tid; e < Ee; e += GRID * TPB) {
        int d = adj[Ee + e];
        int p = atomicAdd(&g_cursor[d], 1);
        g_edge_src[p] = adj[e];          // adj[0] = src
    }
    grid_bar();   // ---- barrier 4: edge_src ready ----

    // ================= Phase D: GAT (persistent warps) =================
    for (int n = b * TPB + tid; n < Nn; n += GRID * TPB) g_cursor[n] = 0;  // restore invariant

    int lane = tid & 31;
    int gi = lane >> 3;          // graph within 4-chunk
    int sub = lane & 7;          // channel group: [16*sub, 16*sub+16)
    int h = sub >> 1;            // head
    int gi4h = gi * 4 + h;       // comb sub-offset within chunk
    const __half* __restrict__ embp = g_emb_h;
    const float2* __restrict__ comb = g_comb;

    for (int w = b * 32 + (tid >> 5); w < Nn * 4; w += GRID * 32) {
        int v = w >> 2;              // consecutive warps share v -> L1 hits
        int gc = w & 3;
        int g = gc * 4 + gi;
        int co = gc * 16 + gi4h;     // lane's comb offset within a node's 64-entry row

        // self loop via comb
        float2 uav = comb[v * 64 + co];
        int vemb = __float_as_int(uav.x);
        float adst = g_adst[vemb * 4 + h];

        float acc[16];
        float s;
        {
            float a0 = uav.y + adst;
            a0 = fmaxf(a0, NEG * a0);
            float e0 = fexp2(a0);
            s = e0;
            const uint4* mp = (const uint4*)(embp + vemb * 128 + sub * 16);
            uint4 q0 = mp[0], q1 = mp[1];
            const __half2* hp0 = (const __half2*)&q0;
            const __half2* hp1 = (const __half2*)&q1;
#pragma unroll
            for (int k = 0; k < 4; k++) {
                float2 f0 = __half22float2(hp0[k]);
                float2 f1 = __half22float2(hp1[k]);
                acc[2 * k] = e0 * f0.x;
                acc[2 * k + 1] = e0 * f0.y;
                acc[8 + 2 * k] = e0 * f1.x;
                acc[8 + 2 * k + 1] = e0 * f1.y;
            }
        }

        int idx = g_row_ptr[v];
        int end = g_row_ptr[v + 1];
        // pipeline: comb prefetched 1 edge ahead, edge_src 2 ahead (pad slots read 0 -> valid)
        int j0 = g_edge_src[idx];
        float2 ua_c = comb[j0 * 64 + co];
        int j2 = g_edge_src[idx + 1];
        for (; idx < end; idx++) {
            float2 ua = ua_c;
            ua_c = comb[j2 * 64 + co];
            j2 = g_edge_src[idx + 2];

            int u = __float_as_int(ua.x);
            float a = ua.y + adst;
            const uint4* mp = (const uint4*)(embp + u * 128 + sub * 16);
            uint4 q0 = mp[0], q1 = mp[1];
            a = fmaxf(a, NEG * a);
            float wi = fexp2(a);
            s += wi;
            const __half2* hp0 = (const __half2*)&q0;
            const __half2* hp1 = (const __half2*)&q1;
#pragma unroll
            for (int k = 0; k < 4; k++) {
                float2 f0 = __half22float2(hp0[k]);
                float2 f1 = __half22float2(hp1[k]);
                acc[2 * k]         = fmaf(wi, f0.x, acc[2 * k]);
                acc[2 * k + 1]     = fmaf(wi, f0.y, acc[2 * k + 1]);
                acc[8 + 2 * k]     = fmaf(wi, f1.x, acc[8 + 2 * k]);
                acc[8 + 2 * k + 1] = fmaf(wi, f1.y, acc[8 + 2 * k + 1]);
            }
        }

        float inv = __fdividef(1.f, s + 1e-16f);
        float* op = out + ((size_t)g * Nn + v) * 128 + sub * 16;
        const float* bp = bias + sub * 16;
#pragma unroll
        for (int k = 0; k < 4; k++) {
            float4 bb = *(const float4*)(bp + 4 * k);
            float4 o;
            o.x = fmaf(acc[4 * k], inv, bb.x);
            o.y = fmaf(acc[4 * k + 1], inv, bb.y);
            o.z = fmaf(acc[4 * k + 2], inv, bb.z);
            o.w = fmaf(acc[4 * k + 3], inv, bb.w);
            *(float4*)(op + 4 * k) = o;
        }
    }
}

extern "C" void kernel_launch(void* const* d_in, const int* in_sizes, int n_in,
                              void* d_out, int out_size) {
    const int*   x     = (const int*)d_in[0];     // [B,DAYS,N] = [16,10000]
    const int*   adj   = (const int*)d_in[1];     // [2,E]
    const float* emb   = (const float*)d_in[2];   // [N,32]
    const float* W     = (const float*)d_in[3];   // [32,128]
    const float* att_s = (const float*)d_in[4];   // [4,32]
    const float* att_d = (const float*)d_in[5];   // [4,32]
    const float* bias  = (const float*)d_in[6];   // [128]
    float* out = (float*)d_out;                   // [16,10000,128]

    k_all<<<GRID, TPB>>>(emb, W, att_s, att_d, x, adj, bias, out);
}

// round 10
// speedup vs baseline: 1.3667x; 1.0567x over previous
#include <cuda_runtime.h>
#include <cuda_fp16.h>

// Problem constants (fixed by the reference)
#define Nn   10000      // nodes
#define Ee   80000      // edges (excl. self loops)
#define Gg   16         // B*DAYS graphs
#define HC   128        // H*C_OUT
#define NEG  0.2f
#define PR   8          // rows per proj group
#define NPROJ (Nn / PR)             // 1250 proj groups
#define LOG2E 1.44269504088896f

#define GRID  296       // 2 blocks per SM (148 SMs), co-resident by launch_bounds
#define TPB   768
#define NWRP  24        // warps per block
#define GRPS  6         // 128-thread proj groups per block
#define CHUNK 34        // nodes per block in scan (296*34 >= 10000)

// ---- device scratch (allocation-free rule: __device__ globals) ----
__device__ __align__(16) __half g_emb_h[Nn * HC];     // fp16 projected embedding [N,128]
__device__ __align__(16) float g_asrc[Nn * 4];        // src logits * log2e [N,H]
__device__ __align__(16) float g_adst[Nn * 4];        // dst logits * log2e [N,H]
__device__ __align__(16) int g_xT[Nn * Gg];           // transposed x: [N,16]
__device__ __align__(16) float2 g_comb[Nn * Gg * 4];  // per (n,g,h): {u_bits, asrc[u][h]}
__device__ int g_row_ptr[Nn + 1];
__device__ int g_cursor[Nn];                          // INVARIANT: all-zero at launch entry
__device__ int g_edge_src[Ee + 3];                    // +3 pad (stays 0) for 3-deep prefetch
__device__ int g_bsum[GRID];

// grid barrier: count self-resets; gen is monotonic across launches (replay-safe)
__device__ unsigned g_bcount = 0;
__device__ volatile unsigned g_bgen = 0;

__device__ __forceinline__ void grid_bar() {
    __syncthreads();
    if (threadIdx.x == 0) {
        __threadfence();
        unsigned my = g_bgen;
        unsigned t = atomicAdd(&g_bcount, 1);
        if (t == GRID - 1) {
            g_bcount = 0;
            __threadfence();
            g_bgen = my + 1;
        } else {
            while (g_bgen == my) { }
            __threadfence();
        }
    }
    __syncthreads();
}

__device__ __forceinline__ float fexp2(float x) {
    float y;
    asm("ex2.approx.f32 %0, %1;" : "=f"(y) : "f"(x));
    return y;
}

__global__ void __launch_bounds__(TPB, 2)
k_all(const float* __restrict__ emb, const float* __restrict__ W,
      const float* __restrict__ att_s, const float* __restrict__ att_d,
      const int* __restrict__ x, const int* __restrict__ adj,
      const float* __restrict__ bias, float* __restrict__ out) {
    int tid = threadIdx.x;
    int b = blockIdx.x;

    __shared__ float sws[256];            // fused W@att: [k][(srcdst<<2)|h]
    __shared__ float se[GRPS][PR][32];
    __shared__ int svals[CHUNK];
    __shared__ int soff;

    // ================= Phase A: histogram + projection + x-transpose =================
    for (int e = b * TPB + tid; e < Ee; e += GRID * TPB)
        atomicAdd(&g_cursor[adj[Ee + e]], 1);          // adj[1] = dst

    if (tid < 256) {
        int k = tid >> 3, j = tid & 7, h = j & 3;
        const float* av = (j < 4) ? att_s : att_d;
        float a = 0.f;
#pragma unroll
        for (int c2 = 0; c2 < 32; c2++)
            a = fmaf(W[k * 128 + h * 32 + c2], av[h * 32 + c2], a);
        sws[tid] = a;
    }
    __syncthreads();

    {
        int grp = tid >> 7;          // 0..5
        int c = tid & 127;           // channel 0..127
        int gb = b * GRPS + grp;     // 296*6 = 1776 >= 1250 -> single iteration
        bool act = gb < NPROJ;
        int n0 = gb * PR;
        if (act) {
#pragma unroll
            for (int i = 0; i < 2; i++) {
                int idx = i * 128 + c;
                se[grp][idx >> 5][idx & 31] = emb[n0 * 32 + idx];
            }
            int gg = c >> 3, i = c & 7;
            g_xT[(n0 + i) * Gg + gg] = x[gg * Nn + n0 + i];
        }
        asm volatile("bar.sync %0, %1;" :: "r"(grp + 1), "r"(128));
        if (act) {
            float acc[PR];
#pragma unroll
            for (int r = 0; r < PR; r++) acc[r] = 0.f;
            // two passes of 16 W-column registers (keeps regs under the 42 cap)
#pragma unroll
            for (int pass = 0; pass < 2; pass++) {
                float wcol[16];
#pragma unroll
                for (int k = 0; k < 16; k++) wcol[k] = W[(pass * 16 + k) * 128 + c];
#pragma unroll
                for (int r = 0; r < PR; r++) {
#pragma unroll
                    for (int k = 0; k < 16; k++)
                        acc[r] = fmaf(se[grp][r][pass * 16 + k], wcol[k], acc[r]);
                }
            }
#pragma unroll
            for (int r = 0; r < PR; r++)
                g_emb_h[(n0 + r) * 128 + c] = __float2half(acc[r]);
            if (c < 64) {
                int r = c >> 3, j = c & 7, h = j & 3;
                float a = 0.f;
#pragma unroll
                for (int k = 0; k < 32; k++) a = fmaf(se[grp][r][k], sws[k * 8 + j], a);
                a *= LOG2E;
                if (j < 4) g_asrc[(n0 + r) * 4 + h] = a;
                else       g_adst[(n0 + r) * 4 + h] = a;
            }
        }
    }
    grid_bar();   // ---- barrier 1: histogram + asrc + xT complete ----

    // ================= Phase B: CSR scan (warp 0) + comb table (all threads) =================
    if (tid < 32) {
        int lane = tid;
        int i0 = b * CHUNK + lane * 2;
        int c0 = (lane < 17 && i0 < Nn) ? g_cursor[i0] : 0;
        int c1 = (lane < 17 && i0 + 1 < Nn) ? g_cursor[i0 + 1] : 0;
        int lsum = c0 + c1;
        int pre = lsum;
#pragma unroll
        for (int o = 1; o < 32; o <<= 1) {
            int t = __shfl_up_sync(0xffffffffu, pre, o);
            if (lane >= o) pre += t;
        }
        int excl = pre - lsum;
        if (lane < 17) {
            svals[lane * 2] = excl;
            if (lane * 2 + 1 < CHUNK) svals[lane * 2 + 1] = excl + c0;
        }
        if (lane == 31) g_bsum[b] = pre;   // block total
    }

    // comb: per (n,g): u = xT[n*16+g]; entries h=0..3: {u_bits, asrc[u][h]}
    for (int i = b * TPB + tid; i < Nn * Gg; i += GRID * TPB) {
        int u = g_xT[i];
        float4 a4 = *(const float4*)(g_asrc + u * 4);
        float uf = __int_as_float(u);
        float4* dst = (float4*)(g_comb + i * 4);
        dst[0] = make_float4(uf, a4.x, uf, a4.y);
        dst[1] = make_float4(uf, a4.z, uf, a4.w);
    }
    grid_bar();   // ---- barrier 2: block sums + comb visible ----

    if (tid < 32) {
        int lane = tid;
        int acc = 0;
        for (int i = lane; i < b; i += 32) acc += g_bsum[i];
#pragma unroll
        for (int o = 16; o; o >>= 1) acc += __shfl_down_sync(0xffffffffu, acc, o);
        if (lane == 0) soff = acc;
    }
    __syncthreads();
    {
        int off = soff;
        if (tid < CHUNK) {
            int n = b * CHUNK + tid;
            if (n < Nn) {
                int p = off + svals[tid];
                g_row_ptr[n] = p;
                g_cursor[n] = p;
            }
        }
        if (b == 0 && tid == 0) g_row_ptr[Nn] = Ee;
    }
    grid_bar();   // ---- barrier 3: row_ptr/cursor ready ----

    // ================= Phase C: CSR fill =================
    for (int e = b * TPB + tid; e < Ee; e += GRID * TPB) {
        int d = adj[Ee + e];
        int p = atomicAdd(&g_cursor[d], 1);
        g_edge_src[p] = adj[e];          // adj[0] = src
    }
    grid_bar();   // ---- barrier 4: edge_src ready ----

    // ================= Phase D: GAT (persistent warps) =================
    for (int n = b * TPB + tid; n < Nn; n += GRID * TPB) g_cursor[n] = 0;  // restore invariant

    int lane = tid & 31;
    int gi = lane >> 4;          // graph within 2-chunk
    int sub = lane & 15;         // channel group: [8*sub, 8*sub+8)
    int h = sub >> 2;            // head
    const __half* __restrict__ embp = g_emb_h;
    const float2* __restrict__ comb = g_comb;

    for (int w = b * NWRP + (tid >> 5); w < Nn * 8; w += GRID * NWRP) {
        int v = w >> 3;              // consecutive warps share v -> L1 hits
        int gc = w & 7;              // 2-graph chunk
        int g = gc * 2 + gi;
        int co = g * 4 + h;          // lane's comb entry within node's 64-entry row

        // self loop via comb
        float2 uav = comb[v * 64 + co];
        int vemb = __float_as_int(uav.x);
        float adst = g_adst[vemb * 4 + h];

        float acc[8];
        float s;
        {
            float a0 = uav.y + adst;
            a0 = fmaxf(a0, NEG * a0);
            float e0 = fexp2(a0);
            s = e0;
            uint4 q = *(const uint4*)(embp + vemb * 128 + sub * 8);
            const __half2* hp = (const __half2*)&q;
#pragma unroll
            for (int k = 0; k < 4; k++) {
                float2 f = __half22float2(hp[k]);
                acc[2 * k] = e0 * f.x;
                acc[2 * k + 1] = e0 * f.y;
            }
        }

        int idx = g_row_ptr[v];
        int end = g_row_ptr[v + 1];
        // 3-deep pipeline: edge_src +3, comb +2, msg +1 (pad slots read 0 -> valid node 0)
        int j0 = g_edge_src[idx];
        int j1 = g_edge_src[idx + 1];
        float2 c0 = comb[j0 * 64 + co];
        float2 c1 = comb[j1 * 64 + co];
        uint4 m0 = *(const uint4*)(embp + __float_as_int(c0.x) * 128 + sub * 8);
        int j2 = g_edge_src[idx + 2];
        for (; idx < end; idx++) {
            // prefetch next message + comb
            uint4 m1 = *(const uint4*)(embp + __float_as_int(c1.x) * 128 + sub * 8);
            float a = c0.y + adst;
            c0 = c1;
            c1 = comb[j2 * 64 + co];
            j2 = g_edge_src[idx + 3];

            a = fmaxf(a, NEG * a);
            float wi = fexp2(a);
            s += wi;
            const __half2* hp = (const __half2*)&m0;
#pragma unroll
            for (int k = 0; k < 4; k++) {
                float2 f = __half22float2(hp[k]);
                acc[2 * k]     = fmaf(wi, f.x, acc[2 * k]);
                acc[2 * k + 1] = fmaf(wi, f.y, acc[2 * k + 1]);
            }
            m0 = m1;
        }

        float inv = __fdividef(1.f, s + 1e-16f);
        float* op = out + ((size_t)g * Nn + v) * 128 + sub * 8;
        const float* bp = bias + sub * 8;
#pragma unroll
        for (int k = 0; k < 2; k++) {
            float4 bb = *(const float4*)(bp + 4 * k);
            float4 o;
            o.x = fmaf(acc[4 * k], inv, bb.x);
            o.y = fmaf(acc[4 * k + 1], inv, bb.y);
            o.z = fmaf(acc[4 * k + 2], inv, bb.z);
            o.w = fmaf(acc[4 * k + 3], inv, bb.w);
            *(float4*)(op + 4 * k) = o;
        }
    }
}

extern "C" void kernel_launch(void* const* d_in, const int* in_sizes, int n_in,
                              void* d_out, int out_size) {
    const int*   x     = (const int*)d_in[0];     // [B,DAYS,N] = [16,10000]
    const int*   adj   = (const int*)d_in[1];     // [2,E]
    const float* emb   = (const float*)d_in[2];   // [N,32]
    const float* W     = (const float*)d_in[3];   // [32,128]
    const float* att_s = (const float*)d_in[4];   // [4,32]
    const float* att_d = (const float*)d_in[5];   // [4,32]
    const float* bias  = (const float*)d_in[6];   // [128]
    float* out = (float*)d_out;                   // [16,10000,128]

    k_all<<<GRID, TPB>>>(emb, W, att_s, att_d, x, adj, bias, out);
}